// round 9
// baseline (speedup 1.0000x reference)
#include <cuda_runtime.h>
#include <cuda_bf16.h>
#include <cstdint>

// ===================== problem constants =====================
constexpr int Nn = 8192;
constexpr int Dd = 768;
constexpr int BM = 256;            // Q rows per CTA
constexpr int BN = 128;            // C cols per tile
constexpr int BK = 128;            // K per SMEM chunk (128 s8 = 128B rows)
constexpr int NKC = Dd / BK;       // 6 K-chunks
constexpr int COLSPLIT = 4;        // grid.y
constexpr int CHUNKS = (Nn / BN) / COLSPLIT;  // 16 col tiles per CTA
constexpr int TOT = CHUNKS * NKC;  // 96 B-chunk iterations
constexpr float D2SC = 28.853900817779268f;   // 20*log2(e)
constexpr float LN2 = 0.6931471805599453f;

constexpr int A_BYTES = BM * Dd;                     // 196608 (6 chunks of 32KB)
constexpr int B_OFF   = A_BYTES;
constexpr int B_BUF   = BN * BK;                     // 16384
constexpr int SMEM_BYTES = A_BYTES + 2 * B_BUF;      // 229376

// ===================== device scratch =====================
__device__ __align__(16) uint8_t g_q8[(size_t)Nn * Dd];
__device__ __align__(16) uint8_t g_c8[(size_t)Nn * Dd];
__device__ float g_qs[Nn];     // D2SC / Sq[row]
__device__ float g_cs[Nn];     // 1 / Sc[row]
__device__ float g_rows[COLSPLIT][Nn];
__device__ float g_diag[Nn];   // exact fp32 diagonal, base-2 scaled

// ===================== helpers =====================
__device__ __forceinline__ uint32_t smem_u32(const void* p) {
    uint32_t a;
    asm("{ .reg .u64 t; cvta.to.shared.u64 t, %1; cvt.u32.u64 %0, t; }"
        : "=r"(a) : "l"(p));
    return a;
}

#define SMEM_SWIZZLE_128B(o) ((o) ^ (((o) >> 3) & 0x70))

__device__ __forceinline__ void cp16(uint32_t dst, const void* src) {
    asm volatile("cp.async.cg.shared.global [%0], [%1], 16;" :: "r"(dst), "l"(src));
}
#define CP_COMMIT asm volatile("cp.async.commit_group;" ::: "memory")
#define CP_WAIT0  asm volatile("cp.async.wait_group 0;" ::: "memory")

__device__ __forceinline__ void ldm4(uint32_t* r, uint32_t addr) {
    asm volatile("ldmatrix.sync.aligned.m8n8.x4.shared.b16 {%0,%1,%2,%3}, [%4];"
        : "=r"(r[0]), "=r"(r[1]), "=r"(r[2]), "=r"(r[3]) : "r"(addr));
}

// int8 IMMA: m16n8k32, fragment byte-layout identical to bf16 m16n8k16
__device__ __forceinline__ void imma16832(int* d, const uint32_t* a,
                                          uint32_t b0, uint32_t b1) {
    asm volatile(
        "mma.sync.aligned.m16n8k32.row.col.s32.s8.s8.s32 "
        "{%0,%1,%2,%3}, {%4,%5,%6,%7}, {%8,%9}, {%0,%1,%2,%3};"
        : "+r"(d[0]), "+r"(d[1]), "+r"(d[2]), "+r"(d[3])
        : "r"(a[0]), "r"(a[1]), "r"(a[2]), "r"(a[3]), "r"(b0), "r"(b1));
}

__device__ __forceinline__ float ex2f(float x) {
    float y;
    asm("ex2.approx.f32 %0, %1;" : "=f"(y) : "f"(x));
    return y;
}

// ===== kernel 1: normalize fp32 -> s8 (per-row max scale), exact diagonal =====
__global__ void __launch_bounds__(256) norm_kernel(const float* __restrict__ q,
                                                   const float* __restrict__ c) {
    const int row = blockIdx.x;  // 0..8191
    const int tid = threadIdx.x;
    const float* qs = q + (size_t)row * Dd;
    const float* cs = c + (size_t)row * Dd;

    float qv[3], cv[3];
    float qq = 0.f, cc = 0.f, qc = 0.f, mq = 0.f, mc = 0.f;
#pragma unroll
    for (int i = 0; i < 3; i++) {
        qv[i] = qs[tid + i * 256];
        cv[i] = cs[tid + i * 256];
        qq += qv[i] * qv[i];
        cc += cv[i] * cv[i];
        qc += qv[i] * cv[i];
        mq = fmaxf(mq, fabsf(qv[i]));
        mc = fmaxf(mc, fabsf(cv[i]));
    }
#pragma unroll
    for (int o = 16; o; o >>= 1) {
        qq += __shfl_xor_sync(0xFFFFFFFFu, qq, o);
        cc += __shfl_xor_sync(0xFFFFFFFFu, cc, o);
        qc += __shfl_xor_sync(0xFFFFFFFFu, qc, o);
        mq = fmaxf(mq, __shfl_xor_sync(0xFFFFFFFFu, mq, o));
        mc = fmaxf(mc, __shfl_xor_sync(0xFFFFFFFFu, mc, o));
    }
    __shared__ float sred[8][5];
    if ((tid & 31) == 0) {
        sred[tid >> 5][0] = qq;
        sred[tid >> 5][1] = cc;
        sred[tid >> 5][2] = qc;
        sred[tid >> 5][3] = mq;
        sred[tid >> 5][4] = mc;
    }
    __syncthreads();
    float tq = 0.f, tc = 0.f, tqc = 0.f, tmq = 0.f, tmc = 0.f;
#pragma unroll
    for (int i = 0; i < 8; i++) {
        tq += sred[i][0]; tc += sred[i][1]; tqc += sred[i][2];
        tmq = fmaxf(tmq, sred[i][3]); tmc = fmaxf(tmc, sred[i][4]);
    }
    const float nq = fmaxf(sqrtf(tq), 1e-8f);
    const float nc = fmaxf(sqrtf(tc), 1e-8f);
    // per-row int8 scales: Sq maps max|element/norm| -> 126
    const float Sq = 126.0f * nq / fmaxf(tmq, 1e-20f);   // multiply raw by Sq/nq
    const float Sc = 126.0f * nc / fmaxf(tmc, 1e-20f);
    if (tid == 0) {
        g_diag[row] = D2SC * tqc / (nq * nc);
        g_qs[row] = D2SC / Sq;
        g_cs[row] = 1.0f / Sc;
    }

    const float fq = Sq / nq, fc = Sc / nc;
    uint8_t* q8 = g_q8 + (size_t)row * Dd;
    uint8_t* c8 = g_c8 + (size_t)row * Dd;
#pragma unroll
    for (int i = 0; i < 3; i++) {
        int iq = __float2int_rn(qv[i] * fq);
        int ic = __float2int_rn(cv[i] * fc);
        iq = max(-127, min(127, iq));
        ic = max(-127, min(127, ic));
        q8[tid + i * 256] = (uint8_t)(int8_t)iq;
        c8[tid + i * 256] = (uint8_t)(int8_t)ic;
    }
}

// ===================== kernel 2: fused s8 GEMM + exp2-rowsum =====================
// 8 warps: 4 (M) x 2 (N), 64x64 warp tiles over a 256x128 CTA tile.
__global__ void __launch_bounds__(256, 1) simcse_main() {
    extern __shared__ __align__(1024) uint8_t smem[];
    uint8_t* sA = smem;           // 6 chunks of [256 rows][128B] SW128 K-major
    uint8_t* sB = smem + B_OFF;   // 2 buffers of [128 rows][128B] SW128 K-major

    const int tid = threadIdx.x;
    const int lane = tid & 31;
    const int wid = tid >> 5;
    const int warp_m = wid >> 1;   // 0..3 (64 rows each)
    const int warp_n = wid & 1;    // 0..1 (64 cols each)
    const int bx = blockIdx.x;     // row block 0..31
    const int by = blockIdx.y;     // col split 0..3
    const int q8l = lane >> 2, tt = lane & 3;

    const uint32_t sA_u = smem_u32(sA);
    const uint32_t sB_u = smem_u32(sB);

    // ---- stage A: this CTA's 256 Q rows (192KB s8) via cp.async ----
    {
        const uint8_t* qbase = g_q8 + (size_t)bx * BM * Dd;
#pragma unroll 4
        for (int i = 0; i < 48; i++) {
            int idx = tid + i * 256;        // 0..12287 (16B units)
            int kc = idx >> 11;             // chunk (2048 units = 32KB)
            int pos = idx & 2047;
            int r = pos >> 3, c = pos & 7;
            const void* src = qbase + (size_t)r * Dd + kc * BK + c * 16;
            uint32_t dst = sA_u + kc * 32768 +
                           SMEM_SWIZZLE_128B((uint32_t)(r * 128 + c * 16));
            cp16(dst, src);
        }
    }

    const uint8_t* cquad = g_c8 + (size_t)by * CHUNKS * BN * Dd;

    auto loadB = [&](int g, int buf) {
        const int t = g / NKC, kc = g % NKC;
        const uint8_t* cb = cquad + (size_t)t * BN * Dd + kc * BK;
#pragma unroll
        for (int i = 0; i < 4; i++) {
            int pos = tid + i * 256;        // 0..1023
            int r = pos >> 3, c = pos & 7;
            cp16(sB_u + buf * B_BUF +
                     SMEM_SWIZZLE_128B((uint32_t)(r * 128 + c * 16)),
                 cb + (size_t)r * Dd + c * 16);
        }
        CP_COMMIT;
    };

    loadB(0, 0);  // (A's cp.asyncs join this commit group)

    // per-lane row factors (8 rows: mt x h), loaded once
    float aqr[8];
#pragma unroll
    for (int mt = 0; mt < 4; mt++)
#pragma unroll
        for (int h = 0; h < 2; h++)
            aqr[mt * 2 + h] = __ldg(&g_qs[bx * BM + warp_m * 64 + mt * 16 + h * 8 + q8l]);

    // per-lane ldmatrix base offsets (bytes, pre-swizzle) — R6-validated
    const uint32_t aoff0 = (uint32_t)((warp_m * 64 + (lane & 15)) * 128 +
                                      (lane >> 4) * 16);
    const uint32_t boff0 = (uint32_t)(((((lane >> 4) & 1) * 8) + (lane & 7)) * 128 +
                                      ((lane >> 3) & 1) * 16) +
                           (uint32_t)warp_n * 8192u;

    int acc[4][8][4];
#pragma unroll
    for (int mt = 0; mt < 4; mt++)
#pragma unroll
        for (int nt = 0; nt < 8; nt++)
#pragma unroll
            for (int d = 0; d < 4; d++) acc[mt][nt][d] = 0;

    float rsum[4][2];
#pragma unroll
    for (int mt = 0; mt < 4; mt++) { rsum[mt][0] = 0.f; rsum[mt][1] = 0.f; }

#pragma unroll 1
    for (int g = 0; g < TOT; g++) {
        const int buf = g & 1;
        CP_WAIT0;            // this chunk's B tile (and A on g==0) is resident
        __syncthreads();     // everyone done reading buf^1 (chunk g-1)
        if (g + 1 < TOT) loadB(g + 1, buf ^ 1);

        const uint32_t abase = sA_u + (uint32_t)(g % NKC) * 32768u;
        const uint32_t bbase = sB_u + (uint32_t)buf * (uint32_t)B_BUF;

        uint32_t a[2][4][4], b[2][4][4];
        // prefetch kk=0 fragments
#pragma unroll
        for (int mt = 0; mt < 4; mt++)
            ldm4(a[0][mt], abase + SMEM_SWIZZLE_128B(aoff0 + (uint32_t)(mt * 2048)));
#pragma unroll
        for (int ntp = 0; ntp < 4; ntp++)
            ldm4(b[0][ntp], bbase + SMEM_SWIZZLE_128B(boff0 + (uint32_t)(ntp * 2048)));

#pragma unroll
        for (int kk = 0; kk < 4; kk++) {   // 4 x k32 per 128-k chunk
            const int cur = kk & 1, nxt = cur ^ 1;
            if (kk < 3) {
#pragma unroll
                for (int mt = 0; mt < 4; mt++)
                    ldm4(a[nxt][mt], abase + SMEM_SWIZZLE_128B(
                             aoff0 + (uint32_t)(mt * 2048 + (kk + 1) * 32)));
#pragma unroll
                for (int ntp = 0; ntp < 4; ntp++)
                    ldm4(b[nxt][ntp], bbase + SMEM_SWIZZLE_128B(
                             boff0 + (uint32_t)(ntp * 2048 + (kk + 1) * 32)));
            }
#pragma unroll
            for (int mt = 0; mt < 4; mt++)
#pragma unroll
                for (int ntp = 0; ntp < 4; ntp++) {
                    imma16832(acc[mt][2 * ntp + 0], a[cur][mt],
                              b[cur][ntp][0], b[cur][ntp][1]);
                    imma16832(acc[mt][2 * ntp + 1], a[cur][mt],
                              b[cur][ntp][2], b[cur][ntp][3]);
                }
        }

        if ((g % NKC) == NKC - 1) {
            const int t = g / NKC;
            // per-lane col factors for this tile (16 cols: nt x b)
            const float* csb = g_cs + ((size_t)(by * CHUNKS + t) * BN +
                                       warp_n * 64 + tt * 2);
            float acf[16];
#pragma unroll
            for (int nt = 0; nt < 8; nt++) {
                acf[nt * 2 + 0] = __ldg(csb + nt * 8 + 0);
                acf[nt * 2 + 1] = __ldg(csb + nt * 8 + 1);
            }
            // epilogue: int->float, row*col scale to base-2 logits, exp2, rowsum
#pragma unroll
            for (int mt = 0; mt < 4; mt++)
#pragma unroll
                for (int nt = 0; nt < 8; nt++)
#pragma unroll
                    for (int d = 0; d < 4; d++) {
                        float l = (float)acc[mt][nt][d] *
                                  aqr[mt * 2 + (d >> 1)] * acf[nt * 2 + (d & 1)];
                        rsum[mt][d >> 1] += ex2f(l);
                        acc[mt][nt][d] = 0;
                    }
        }
    }

    // ---- reduce row sums: quad shuffle, then across the 2 N-warps via SMEM ----
#pragma unroll
    for (int mt = 0; mt < 4; mt++)
#pragma unroll
        for (int h = 0; h < 2; h++) {
            float v = rsum[mt][h];
            v += __shfl_xor_sync(0xFFFFFFFFu, v, 1);
            v += __shfl_xor_sync(0xFFFFFFFFu, v, 2);
            rsum[mt][h] = v;
        }

    float* sred = (float*)smem;  // reuse A region (2KB): [256 rows][2 warp_n]
    __syncthreads();
    if (tt == 0) {
#pragma unroll
        for (int mt = 0; mt < 4; mt++)
#pragma unroll
            for (int h = 0; h < 2; h++) {
                int rl = warp_m * 64 + mt * 16 + h * 8 + q8l;
                sred[rl * 2 + warp_n] = rsum[mt][h];
            }
    }
    __syncthreads();
    g_rows[by][bx * BM + tid] = sred[tid * 2] + sred[tid * 2 + 1];
}

// ===================== kernel 3: loss reduction =====================
__global__ void __launch_bounds__(256) loss_kernel(float* __restrict__ out) {
    int tid = threadIdx.x;
    float acc = 0.f;
    for (int i = tid; i < Nn; i += 256) {
        float r = g_rows[0][i] + g_rows[1][i] + g_rows[2][i] + g_rows[3][i];
        acc += logf(r) - g_diag[i] * LN2;   // diag is base-2 scaled (exact fp32)
    }
#pragma unroll
    for (int o = 16; o; o >>= 1) acc += __shfl_xor_sync(0xFFFFFFFFu, acc, o);
    __shared__ float sred[8];
    if ((tid & 31) == 0) sred[tid >> 5] = acc;
    __syncthreads();
    if (tid == 0) {
        float tot = 0.f;
#pragma unroll
        for (int i = 0; i < 8; i++) tot += sred[i];
        out[0] = tot * (1.0f / (float)Nn);
    }
}

// ===================== launch =====================
extern "C" void kernel_launch(void* const* d_in, const int* in_sizes, int n_in,
                              void* d_out, int out_size) {
    const float* q = (const float*)d_in[0];
    const float* c = (const float*)d_in[1];
    float* out = (float*)d_out;

    cudaFuncSetAttribute(simcse_main, cudaFuncAttributeMaxDynamicSharedMemorySize,
                         SMEM_BYTES);

    norm_kernel<<<Nn, 256>>>(q, c);
    simcse_main<<<dim3(Nn / BM, COLSPLIT), 256, SMEM_BYTES>>>();
    loss_kernel<<<1, 256>>>(out);
}

// round 10
// speedup vs baseline: 2.6341x; 2.6341x over previous
#include <cuda_runtime.h>
#include <cuda_bf16.h>
#include <cstdint>

// ===================== problem constants =====================
constexpr int Nn = 8192;
constexpr int Dd = 768;
constexpr int BM = 128;            // Q rows per job
constexpr int BN = 128;            // C cols per tile
constexpr int BK = 64;             // K per SMEM chunk (64 bf16 = 128B rows)
constexpr int NKC = Dd / BK;       // 12 K-chunks
constexpr int COLSPLIT = 16;       // by range
constexpr int CHUNKS = (Nn / BN) / COLSPLIT;  // 4 col tiles per job
constexpr int TOT = CHUNKS * NKC;  // 48 B-chunk iterations per job
constexpr int NJOBS = (Nn / BM) * COLSPLIT;   // 1024
// q rows pre-scaled by 20*log2(e): accumulators are base-2 logits directly
constexpr float QSCALE = 20.0f * 1.4426950408889634f;
constexpr float D2SC = 28.853900817779268f;   // 20*log2(e)
constexpr float LN2 = 0.6931471805599453f;

constexpr int A_BYTES = BM * Dd * 2;                    // 196608
constexpr int B_OFF   = A_BYTES;
constexpr int SMEM_BYTES = A_BYTES + 2 * BN * BK * 2;   // 229376

// ===================== device scratch =====================
__device__ __align__(16) __nv_bfloat16 g_qn[(size_t)Nn * Dd];
__device__ __align__(16) __nv_bfloat16 g_cn[(size_t)Nn * Dd];
__device__ float g_rows[COLSPLIT][Nn];
__device__ float g_diag[Nn];   // exact fp32 diagonal, base-2 scaled

// ===================== helpers =====================
__device__ __forceinline__ uint32_t smem_u32(const void* p) {
    uint32_t a;
    asm("{ .reg .u64 t; cvta.to.shared.u64 t, %1; cvt.u32.u64 %0, t; }"
        : "=r"(a) : "l"(p));
    return a;
}

#define SMEM_SWIZZLE_128B(o) ((o) ^ (((o) >> 3) & 0x70))

__device__ __forceinline__ void cp16(uint32_t dst, const void* src) {
    asm volatile("cp.async.cg.shared.global [%0], [%1], 16;" :: "r"(dst), "l"(src));
}
#define CP_COMMIT asm volatile("cp.async.commit_group;" ::: "memory")
#define CP_WAIT0  asm volatile("cp.async.wait_group 0;" ::: "memory")

__device__ __forceinline__ void ldm4(uint32_t* r, uint32_t addr) {
    asm volatile("ldmatrix.sync.aligned.m8n8.x4.shared.b16 {%0,%1,%2,%3}, [%4];"
        : "=r"(r[0]), "=r"(r[1]), "=r"(r[2]), "=r"(r[3]) : "r"(addr));
}

__device__ __forceinline__ void mma16816(float* d, const uint32_t* a,
                                         uint32_t b0, uint32_t b1) {
    asm volatile(
        "mma.sync.aligned.m16n8k16.row.col.f32.bf16.bf16.f32 "
        "{%0,%1,%2,%3}, {%4,%5,%6,%7}, {%8,%9}, {%0,%1,%2,%3};"
        : "+f"(d[0]), "+f"(d[1]), "+f"(d[2]), "+f"(d[3])
        : "r"(a[0]), "r"(a[1]), "r"(a[2]), "r"(a[3]), "r"(b0), "r"(b1));
}

__device__ __forceinline__ float ex2f(float x) {
    float y;
    asm("ex2.approx.f32 %0, %1;" : "=f"(y) : "f"(x));
    return y;
}

// ===== kernel 1: normalize fp32 -> bf16 (q pre-scaled), exact diagonal =====
__global__ void __launch_bounds__(256) norm_kernel(const float* __restrict__ q,
                                                   const float* __restrict__ c) {
    const int row = blockIdx.x;  // 0..8191
    const int tid = threadIdx.x;
    const float* qs = q + (size_t)row * Dd;
    const float* cs = c + (size_t)row * Dd;

    float qv[3], cv[3];
    float qq = 0.f, cc = 0.f, qc = 0.f;
#pragma unroll
    for (int i = 0; i < 3; i++) {
        qv[i] = qs[tid + i * 256];
        cv[i] = cs[tid + i * 256];
        qq += qv[i] * qv[i];
        cc += cv[i] * cv[i];
        qc += qv[i] * cv[i];
    }
#pragma unroll
    for (int o = 16; o; o >>= 1) {
        qq += __shfl_xor_sync(0xFFFFFFFFu, qq, o);
        cc += __shfl_xor_sync(0xFFFFFFFFu, cc, o);
        qc += __shfl_xor_sync(0xFFFFFFFFu, qc, o);
    }
    __shared__ float sred[8][3];
    if ((tid & 31) == 0) {
        sred[tid >> 5][0] = qq;
        sred[tid >> 5][1] = cc;
        sred[tid >> 5][2] = qc;
    }
    __syncthreads();
    float tq = 0.f, tc = 0.f, tqc = 0.f;
#pragma unroll
    for (int i = 0; i < 8; i++) {
        tq += sred[i][0]; tc += sred[i][1]; tqc += sred[i][2];
    }
    const float nq = fmaxf(sqrtf(tq), 1e-8f);
    const float nc = fmaxf(sqrtf(tc), 1e-8f);
    if (tid == 0) g_diag[row] = D2SC * tqc / (nq * nc);

    const float sq = QSCALE / nq, sc = 1.0f / nc;
    __nv_bfloat16* qd = g_qn + (size_t)row * Dd;
    __nv_bfloat16* cd = g_cn + (size_t)row * Dd;
#pragma unroll
    for (int i = 0; i < 3; i++) {
        qd[tid + i * 256] = __float2bfloat16(qv[i] * sq);
        cd[tid + i * 256] = __float2bfloat16(cv[i] * sc);
    }
}

// ===================== kernel 2: persistent fused GEMM + exp2-rowsum =====================
// grid = #SMs. Each CTA owns a contiguous span of the 1024 (bx,by) jobs
// (bx-major), so consecutive jobs reuse the staged A tile.
// 8 warps: 4 (M) x 2 (N), 32x64 warp tiles (R5-validated mapping).
__global__ void __launch_bounds__(256, 1) simcse_main() {
    extern __shared__ __align__(1024) uint8_t smem[];
    uint8_t* sA = smem;           // 12 chunks of [128 rows][128B] SW128 K-major
    uint8_t* sB = smem + B_OFF;   // 2 buffers of [128 rows][128B] SW128 K-major

    const int tid = threadIdx.x;
    const int lane = tid & 31;
    const int wid = tid >> 5;
    const int warp_m = wid >> 1;   // 0..3 (32 rows each)
    const int warp_n = wid & 1;    // 0..1 (64 cols each)

    const uint32_t sA_u = smem_u32(sA);
    const uint32_t sB_u = smem_u32(sB);

    // per-lane ldmatrix base offsets (bytes, pre-swizzle) — R2/R5-validated
    const uint32_t aoff0 = (uint32_t)((lane & 15) * 128 + (lane >> 4) * 16) +
                           (uint32_t)warp_m * 4096u;
    const uint32_t boff0 = (uint32_t)(((((lane >> 4) & 1) * 8) + (lane & 7)) * 128 +
                                      ((lane >> 3) & 1) * 16) +
                           (uint32_t)warp_n * 8192u;

    const int ncta = gridDim.x;
    const int lo = (int)(((long long)blockIdx.x * NJOBS) / ncta);
    const int hi = (int)(((long long)(blockIdx.x + 1) * NJOBS) / ncta);
    int prev_bx = -1;

    float acc[2][8][4];
#pragma unroll
    for (int mt = 0; mt < 2; mt++)
#pragma unroll
        for (int nt = 0; nt < 8; nt++)
#pragma unroll
            for (int d = 0; d < 4; d++) acc[mt][nt][d] = 0.f;

#pragma unroll 1
    for (int job = lo; job < hi; job++) {
        const int bx = job >> 4;       // row block 0..63
        const int by = job & 15;       // col split 0..15

        // ---- stage A on bx change: 128 Q rows (192KB) via cp.async ----
        if (bx != prev_bx) {
            const __nv_bfloat16* qbase = g_qn + (size_t)bx * BM * Dd;
#pragma unroll 4
            for (int i = 0; i < 48; i++) {
                int idx = tid + i * 256;        // 0..12287 (16B units)
                int kc = idx >> 10;
                int pos = idx & 1023;
                int r = pos >> 3, c = pos & 7;
                const void* src = qbase + (size_t)r * Dd + kc * BK + c * 8;
                uint32_t dst = sA_u + kc * 16384 +
                               SMEM_SWIZZLE_128B((uint32_t)(r * 128 + c * 16));
                cp16(dst, src);
            }
            prev_bx = bx;
        }

        const __nv_bfloat16* cquad = g_cn + (size_t)by * CHUNKS * BN * Dd;

        auto loadB = [&](int g, int buf) {
            const int t = g / NKC, kc = g % NKC;
            const __nv_bfloat16* cb = cquad + (size_t)t * BN * Dd + kc * BK;
#pragma unroll
            for (int i = 0; i < 4; i++) {
                int pos = tid + i * 256;        // 0..1023
                int r = pos >> 3, c = pos & 7;
                cp16(sB_u + buf * 16384 +
                         SMEM_SWIZZLE_128B((uint32_t)(r * 128 + c * 16)),
                     cb + (size_t)r * Dd + c * 8);
            }
            CP_COMMIT;
        };

        loadB(0, 0);  // (A's cp.asyncs, if any, join this commit group)

        float rsum[2][2] = {{0.f, 0.f}, {0.f, 0.f}};

#pragma unroll 1
        for (int g = 0; g < TOT; g++) {
            const int buf = g & 1;
            CP_WAIT0;            // this chunk's B tile (and A if staged) resident
            __syncthreads();     // everyone done reading buf^1 (chunk g-1)
            if (g + 1 < TOT) loadB(g + 1, buf ^ 1);

            const uint32_t abase = sA_u + (uint32_t)(g % NKC) * 16384u;
            const uint32_t bbase = sB_u + (uint32_t)buf * 16384u;

            uint32_t a[2][2][4], b[2][4][4];
            // prefetch kk=0 fragments
#pragma unroll
            for (int mt = 0; mt < 2; mt++)
                ldm4(a[0][mt], abase + SMEM_SWIZZLE_128B(aoff0 + (uint32_t)(mt * 2048)));
#pragma unroll
            for (int ntp = 0; ntp < 4; ntp++)
                ldm4(b[0][ntp], bbase + SMEM_SWIZZLE_128B(boff0 + (uint32_t)(ntp * 2048)));

#pragma unroll
            for (int kk = 0; kk < 4; kk++) {
                const int cur = kk & 1, nxt = cur ^ 1;
                if (kk < 3) {
#pragma unroll
                    for (int mt = 0; mt < 2; mt++)
                        ldm4(a[nxt][mt], abase + SMEM_SWIZZLE_128B(
                                 aoff0 + (uint32_t)(mt * 2048 + (kk + 1) * 32)));
#pragma unroll
                    for (int ntp = 0; ntp < 4; ntp++)
                        ldm4(b[nxt][ntp], bbase + SMEM_SWIZZLE_128B(
                                 boff0 + (uint32_t)(ntp * 2048 + (kk + 1) * 32)));
                }
#pragma unroll
                for (int mt = 0; mt < 2; mt++)
#pragma unroll
                    for (int ntp = 0; ntp < 4; ntp++) {
                        mma16816(acc[mt][2 * ntp + 0], a[cur][mt],
                                 b[cur][ntp][0], b[cur][ntp][1]);
                        mma16816(acc[mt][2 * ntp + 1], a[cur][mt],
                                 b[cur][ntp][2], b[cur][ntp][3]);
                    }
            }

            if ((g % NKC) == NKC - 1) {
                // epilogue: exp2 of base-2 logits, row partial sums
#pragma unroll
                for (int mt = 0; mt < 2; mt++)
#pragma unroll
                    for (int nt = 0; nt < 8; nt++)
#pragma unroll
                        for (int d = 0; d < 4; d++) {
                            rsum[mt][d >> 1] += ex2f(acc[mt][nt][d]);
                            acc[mt][nt][d] = 0.f;
                        }
            }
        }

        // ---- per-job reduce: quad shuffle, then across the 2 N-warps ----
#pragma unroll
        for (int mt = 0; mt < 2; mt++)
#pragma unroll
            for (int h = 0; h < 2; h++) {
                float v = rsum[mt][h];
                v += __shfl_xor_sync(0xFFFFFFFFu, v, 1);
                v += __shfl_xor_sync(0xFFFFFFFFu, v, 2);
                rsum[mt][h] = v;
            }

        float* sred = (float*)sB;    // B buffers are free after last chunk
        __syncthreads();             // all warps done with compute/B reads
        if ((lane & 3) == 0) {
#pragma unroll
            for (int mt = 0; mt < 2; mt++)
#pragma unroll
                for (int h = 0; h < 2; h++) {
                    int rl = warp_m * 32 + mt * 16 + h * 8 + (lane >> 2);
                    sred[rl * 2 + warp_n] = rsum[mt][h];
                }
        }
        __syncthreads();
        if (tid < BM) g_rows[by][bx * BM + tid] = sred[tid * 2] + sred[tid * 2 + 1];
        __syncthreads();  // sred reads done before next job's loadB overwrites sB
    }
}

// ===================== kernel 3: loss reduction =====================
__global__ void __launch_bounds__(256) loss_kernel(float* __restrict__ out) {
    int tid = threadIdx.x;
    float acc = 0.f;
    for (int i = tid; i < Nn; i += 256) {
        float r = 0.f;
#pragma unroll
        for (int s = 0; s < COLSPLIT; s++) r += g_rows[s][i];
        acc += logf(r) - g_diag[i] * LN2;   // diag is base-2 scaled (exact fp32)
    }
#pragma unroll
    for (int o = 16; o; o >>= 1) acc += __shfl_xor_sync(0xFFFFFFFFu, acc, o);
    __shared__ float sred[8];
    if ((tid & 31) == 0) sred[tid >> 5] = acc;
    __syncthreads();
    if (tid == 0) {
        float tot = 0.f;
#pragma unroll
        for (int i = 0; i < 8; i++) tot += sred[i];
        out[0] = tot * (1.0f / (float)Nn);
    }
}

// ===================== launch =====================
extern "C" void kernel_launch(void* const* d_in, const int* in_sizes, int n_in,
                              void* d_out, int out_size) {
    const float* q = (const float*)d_in[0];
    const float* c = (const float*)d_in[1];
    float* out = (float*)d_out;

    cudaFuncSetAttribute(simcse_main, cudaFuncAttributeMaxDynamicSharedMemorySize,
                         SMEM_BYTES);

    int nsm = 148;
    cudaDeviceGetAttribute(&nsm, cudaDevAttrMultiProcessorCount, 0);
    if (nsm < 1) nsm = 148;

    norm_kernel<<<Nn, 256>>>(q, c);
    simcse_main<<<nsm, 256, SMEM_BYTES>>>();
    loss_kernel<<<1, 256>>>(out);
}

// round 12
// speedup vs baseline: 2.6964x; 1.0237x over previous
#include <cuda_runtime.h>
#include <cuda_bf16.h>
#include <cstdint>

// ===================== problem constants =====================
constexpr int Nn = 8192;
constexpr int Dd = 768;
constexpr int BM = 128;            // Q rows per job
constexpr int BN = 128;            // C cols per tile
constexpr int BK = 64;             // K per SMEM chunk (64 bf16 = 128B rows)
constexpr int NKC = Dd / BK;       // 12 K-chunks
constexpr int COLSPLIT = 16;       // by range
constexpr int CHUNKS = (Nn / BN) / COLSPLIT;  // 4 col tiles per job
constexpr int TOT = CHUNKS * NKC;  // 48 B-chunk iterations per job
constexpr int NJOBS = (Nn / BM) * COLSPLIT;   // 1024
// q rows pre-scaled by 20*log2(e): accumulators are base-2 logits directly
constexpr float QSCALE = 20.0f * 1.4426950408889634f;
constexpr float D2SC = 28.853900817779268f;   // 20*log2(e)
constexpr float LN2 = 0.6931471805599453f;

constexpr int A_BYTES = BM * Dd * 2;                    // 196608
constexpr int B_OFF   = A_BYTES;
constexpr int SMEM_BYTES = A_BYTES + 2 * BN * BK * 2;   // 229376

// ===================== device scratch =====================
__device__ __align__(16) __nv_bfloat16 g_qn[(size_t)Nn * Dd];
__device__ __align__(16) __nv_bfloat16 g_cn[(size_t)Nn * Dd];
__device__ float g_rows[COLSPLIT][Nn];
__device__ float g_diag[Nn];   // exact fp32 diagonal, base-2 scaled

// ===================== helpers =====================
__device__ __forceinline__ uint32_t smem_u32(const void* p) {
    uint32_t a;
    asm("{ .reg .u64 t; cvta.to.shared.u64 t, %1; cvt.u32.u64 %0, t; }"
        : "=r"(a) : "l"(p));
    return a;
}

#define SMEM_SWIZZLE_128B(o) ((o) ^ (((o) >> 3) & 0x70))

__device__ __forceinline__ void cp16(uint32_t dst, const void* src) {
    asm volatile("cp.async.cg.shared.global [%0], [%1], 16;" :: "r"(dst), "l"(src));
}
#define CP_COMMIT asm volatile("cp.async.commit_group;" ::: "memory")
#define CP_WAIT0  asm volatile("cp.async.wait_group 0;" ::: "memory")

__device__ __forceinline__ void ldm4(uint32_t* r, uint32_t addr) {
    asm volatile("ldmatrix.sync.aligned.m8n8.x4.shared.b16 {%0,%1,%2,%3}, [%4];"
        : "=r"(r[0]), "=r"(r[1]), "=r"(r[2]), "=r"(r[3]) : "r"(addr));
}

__device__ __forceinline__ void mma16816(float* d, const uint32_t* a,
                                         uint32_t b0, uint32_t b1) {
    asm volatile(
        "mma.sync.aligned.m16n8k16.row.col.f32.bf16.bf16.f32 "
        "{%0,%1,%2,%3}, {%4,%5,%6,%7}, {%8,%9}, {%0,%1,%2,%3};"
        : "+f"(d[0]), "+f"(d[1]), "+f"(d[2]), "+f"(d[3])
        : "r"(a[0]), "r"(a[1]), "r"(a[2]), "r"(a[3]), "r"(b0), "r"(b1));
}

__device__ __forceinline__ float ex2f(float x) {
    float y;
    asm("ex2.approx.f32 %0, %1;" : "=f"(y) : "f"(x));
    return y;
}

// ===== kernel 1: normalize fp32 -> bf16 (q pre-scaled), exact diagonal =====
// One warp per row: float4 loads, shfl-only reduction, packed bf16x2 stores.
__global__ void __launch_bounds__(256) norm_kernel(const float* __restrict__ q,
                                                   const float* __restrict__ c) {
    const int lane = threadIdx.x & 31;
    const int row = blockIdx.x * 8 + (threadIdx.x >> 5);  // 0..8191

    const float4* qs = reinterpret_cast<const float4*>(q + (size_t)row * Dd);
    const float4* cs = reinterpret_cast<const float4*>(c + (size_t)row * Dd);

    float4 qv[6], cv[6];
    float qq = 0.f, cc = 0.f, qc = 0.f;
#pragma unroll
    for (int j = 0; j < 6; j++) {
        qv[j] = qs[lane + j * 32];
        cv[j] = cs[lane + j * 32];
        qq += qv[j].x * qv[j].x + qv[j].y * qv[j].y +
              qv[j].z * qv[j].z + qv[j].w * qv[j].w;
        cc += cv[j].x * cv[j].x + cv[j].y * cv[j].y +
              cv[j].z * cv[j].z + cv[j].w * cv[j].w;
        qc += qv[j].x * cv[j].x + qv[j].y * cv[j].y +
              qv[j].z * cv[j].z + qv[j].w * cv[j].w;
    }
#pragma unroll
    for (int o = 16; o; o >>= 1) {
        qq += __shfl_xor_sync(0xFFFFFFFFu, qq, o);
        cc += __shfl_xor_sync(0xFFFFFFFFu, cc, o);
        qc += __shfl_xor_sync(0xFFFFFFFFu, qc, o);
    }
    const float nq = fmaxf(sqrtf(qq), 1e-8f);
    const float nc = fmaxf(sqrtf(cc), 1e-8f);
    if (lane == 0) g_diag[row] = D2SC * qc / (nq * nc);

    const float sq = QSCALE / nq, sc = 1.0f / nc;
    uint2* qd = reinterpret_cast<uint2*>(g_qn + (size_t)row * Dd);
    uint2* cd = reinterpret_cast<uint2*>(g_cn + (size_t)row * Dd);
#pragma unroll
    for (int j = 0; j < 6; j++) {
        __nv_bfloat162 q0 = __float22bfloat162_rn(
            make_float2(qv[j].x * sq, qv[j].y * sq));
        __nv_bfloat162 q1 = __float22bfloat162_rn(
            make_float2(qv[j].z * sq, qv[j].w * sq));
        __nv_bfloat162 c0 = __float22bfloat162_rn(
            make_float2(cv[j].x * sc, cv[j].y * sc));
        __nv_bfloat162 c1 = __float22bfloat162_rn(
            make_float2(cv[j].z * sc, cv[j].w * sc));
        qd[lane + j * 32] = make_uint2(*(uint32_t*)&q0, *(uint32_t*)&q1);
        cd[lane + j * 32] = make_uint2(*(uint32_t*)&c0, *(uint32_t*)&c1);
    }
}

// ===================== kernel 2: persistent fused GEMM + exp2-rowsum =====================
// grid = #SMs. Each CTA owns a contiguous span of the 1024 (bx,by) jobs
// (bx-major), so consecutive jobs reuse the staged A tile.
// 8 warps: 4 (M) x 2 (N), 32x64 warp tiles (R5/R10-validated mapping).
__global__ void __launch_bounds__(256, 1) simcse_main() {
    extern __shared__ __align__(1024) uint8_t smem[];
    uint8_t* sA = smem;           // 12 chunks of [128 rows][128B] SW128 K-major
    uint8_t* sB = smem + B_OFF;   // 2 buffers of [128 rows][128B] SW128 K-major

    const int tid = threadIdx.x;
    const int lane = tid & 31;
    const int wid = tid >> 5;
    const int warp_m = wid >> 1;   // 0..3 (32 rows each)
    const int warp_n = wid & 1;    // 0..1 (64 cols each)

    const uint32_t sA_u = smem_u32(sA);
    const uint32_t sB_u = smem_u32(sB);

    // per-lane ldmatrix base offsets (bytes, pre-swizzle) — R2/R5-validated
    const uint32_t aoff0 = (uint32_t)((lane & 15) * 128 + (lane >> 4) * 16) +
                           (uint32_t)warp_m * 4096u;
    const uint32_t boff0 = (uint32_t)(((((lane >> 4) & 1) * 8) + (lane & 7)) * 128 +
                                      ((lane >> 3) & 1) * 16) +
                           (uint32_t)warp_n * 8192u;

    const int ncta = gridDim.x;
    const int lo = (int)(((long long)blockIdx.x * NJOBS) / ncta);
    const int hi = (int)(((long long)(blockIdx.x + 1) * NJOBS) / ncta);
    int prev_bx = -1;

    float acc[2][8][4];
#pragma unroll
    for (int mt = 0; mt < 2; mt++)
#pragma unroll
        for (int nt = 0; nt < 8; nt++)
#pragma unroll
            for (int d = 0; d < 4; d++) acc[mt][nt][d] = 0.f;

#pragma unroll 1
    for (int job = lo; job < hi; job++) {
        const int bx = job >> 4;       // row block 0..63
        const int by = job & 15;       // col split 0..15

        // ---- stage A on bx change: 128 Q rows (192KB) via cp.async ----
        if (bx != prev_bx) {
            const __nv_bfloat16* qbase = g_qn + (size_t)bx * BM * Dd;
#pragma unroll 4
            for (int i = 0; i < 48; i++) {
                int idx = tid + i * 256;        // 0..12287 (16B units)
                int kc = idx >> 10;
                int pos = idx & 1023;
                int r = pos >> 3, c = pos & 7;
                const void* src = qbase + (size_t)r * Dd + kc * BK + c * 8;
                uint32_t dst = sA_u + kc * 16384 +
                               SMEM_SWIZZLE_128B((uint32_t)(r * 128 + c * 16));
                cp16(dst, src);
            }
            prev_bx = bx;
        }

        const __nv_bfloat16* cquad = g_cn + (size_t)by * CHUNKS * BN * Dd;

        auto loadB = [&](int g, int buf) {
            const int t = g / NKC, kc = g % NKC;
            const __nv_bfloat16* cb = cquad + (size_t)t * BN * Dd + kc * BK;
#pragma unroll
            for (int i = 0; i < 4; i++) {
                int pos = tid + i * 256;        // 0..1023
                int r = pos >> 3, c = pos & 7;
                cp16(sB_u + buf * 16384 +
                         SMEM_SWIZZLE_128B((uint32_t)(r * 128 + c * 16)),
                     cb + (size_t)r * Dd + c * 8);
            }
            CP_COMMIT;
        };

        loadB(0, 0);  // (A's cp.asyncs, if any, join this commit group)

        float rsum[2][2] = {{0.f, 0.f}, {0.f, 0.f}};

#pragma unroll 1
        for (int g = 0; g < TOT; g++) {
            const int buf = g & 1;
            CP_WAIT0;            // this chunk's B tile (and A if staged) resident
            __syncthreads();     // publish buf to all threads; protect buf^1
            if (g + 1 < TOT) loadB(g + 1, buf ^ 1);

            const uint32_t abase = sA_u + (uint32_t)(g % NKC) * 16384u;
            const uint32_t bbase = sB_u + (uint32_t)buf * 16384u;

            uint32_t a[2][2][4], b[2][4][4];
            // prefetch kk=0 fragments
#pragma unroll
            for (int mt = 0; mt < 2; mt++)
                ldm4(a[0][mt], abase + SMEM_SWIZZLE_128B(aoff0 + (uint32_t)(mt * 2048)));
#pragma unroll
            for (int ntp = 0; ntp < 4; ntp++)
                ldm4(b[0][ntp], bbase + SMEM_SWIZZLE_128B(boff0 + (uint32_t)(ntp * 2048)));

#pragma unroll
            for (int kk = 0; kk < 4; kk++) {
                const int cur = kk & 1, nxt = cur ^ 1;
                if (kk < 3) {
#pragma unroll
                    for (int mt = 0; mt < 2; mt++)
                        ldm4(a[nxt][mt], abase + SMEM_SWIZZLE_128B(
                                 aoff0 + (uint32_t)(mt * 2048 + (kk + 1) * 32)));
#pragma unroll
                    for (int ntp = 0; ntp < 4; ntp++)
                        ldm4(b[nxt][ntp], bbase + SMEM_SWIZZLE_128B(
                                 boff0 + (uint32_t)(ntp * 2048 + (kk + 1) * 32)));
                }
#pragma unroll
                for (int mt = 0; mt < 2; mt++)
#pragma unroll
                    for (int ntp = 0; ntp < 4; ntp++) {
                        mma16816(acc[mt][2 * ntp + 0], a[cur][mt],
                                 b[cur][ntp][0], b[cur][ntp][1]);
                        mma16816(acc[mt][2 * ntp + 1], a[cur][mt],
                                 b[cur][ntp][2], b[cur][ntp][3]);
                    }
            }

            if ((g % NKC) == NKC - 1) {
                // epilogue: exp2 of base-2 logits, row partial sums
#pragma unroll
                for (int mt = 0; mt < 2; mt++)
#pragma unroll
                    for (int nt = 0; nt < 8; nt++)
#pragma unroll
                        for (int d = 0; d < 4; d++) {
                            rsum[mt][d >> 1] += ex2f(acc[mt][nt][d]);
                            acc[mt][nt][d] = 0.f;
                        }
            }
        }

        // ---- per-job reduce: quad shuffle, then across the 2 N-warps ----
#pragma unroll
        for (int mt = 0; mt < 2; mt++)
#pragma unroll
            for (int h = 0; h < 2; h++) {
                float v = rsum[mt][h];
                v += __shfl_xor_sync(0xFFFFFFFFu, v, 1);
                v += __shfl_xor_sync(0xFFFFFFFFu, v, 2);
                rsum[mt][h] = v;
            }

        float* sred = (float*)sB;    // B buffers are free after last chunk
        __syncthreads();             // all warps done with compute/B reads
        if ((lane & 3) == 0) {
#pragma unroll
            for (int mt = 0; mt < 2; mt++)
#pragma unroll
                for (int h = 0; h < 2; h++) {
                    int rl = warp_m * 32 + mt * 16 + h * 8 + (lane >> 2);
                    sred[rl * 2 + warp_n] = rsum[mt][h];
                }
        }
        __syncthreads();
        if (tid < BM) g_rows[by][bx * BM + tid] = sred[tid * 2] + sred[tid * 2 + 1];
        __syncthreads();  // sred reads done before next job's loadB overwrites sB
    }
}

// ===================== kernel 3: loss reduction =====================
__global__ void __launch_bounds__(256) loss_kernel(float* __restrict__ out) {
    int tid = threadIdx.x;
    float acc = 0.f;
    for (int i = tid; i < Nn; i += 256) {
        float r = 0.f;
#pragma unroll
        for (int s = 0; s < COLSPLIT; s++) r += g_rows[s][i];
        acc += logf(r) - g_diag[i] * LN2;   // diag is base-2 scaled (exact fp32)
    }
#pragma unroll
    for (int o = 16; o; o >>= 1) acc += __shfl_xor_sync(0xFFFFFFFFu, acc, o);
    __shared__ float sred[8];
    if ((tid & 31) == 0) sred[tid >> 5] = acc;
    __syncthreads();
    if (tid == 0) {
        float tot = 0.f;
#pragma unroll
        for (int i = 0; i < 8; i++) tot += sred[i];
        out[0] = tot * (1.0f / (float)Nn);
    }
}

// ===================== launch =====================
extern "C" void kernel_launch(void* const* d_in, const int* in_sizes, int n_in,
                              void* d_out, int out_size) {
    const float* q = (const float*)d_in[0];
    const float* c = (const float*)d_in[1];
    float* out = (float*)d_out;

    cudaFuncSetAttribute(simcse_main, cudaFuncAttributeMaxDynamicSharedMemorySize,
                         SMEM_BYTES);

    int nsm = 148;
    cudaDeviceGetAttribute(&nsm, cudaDevAttrMultiProcessorCount, 0);
    if (nsm < 1) nsm = 148;

    norm_kernel<<<Nn / 8, 256>>>(q, c);
    simcse_main<<<nsm, 256, SMEM_BYTES>>>();
    loss_kernel<<<1, 256>>>(out);
}

// round 13
// speedup vs baseline: 2.8030x; 1.0395x over previous
#include <cuda_runtime.h>
#include <cuda_bf16.h>
#include <cstdint>

// ===================== problem constants =====================
constexpr int Nn = 8192;
constexpr int Dd = 768;
constexpr int BM = 128;            // Q rows per job
constexpr int BN = 128;            // C cols per tile
constexpr int BK = 64;             // K per SMEM chunk (64 bf16 = 128B rows)
constexpr int NKC = Dd / BK;       // 12 K-chunks
constexpr int COLSPLIT = 16;       // by range
constexpr int CHUNKS = (Nn / BN) / COLSPLIT;  // 4 col tiles per job
constexpr int TOT = CHUNKS * NKC;  // 48 B-chunk iterations per job
constexpr int NJOBS = (Nn / BM) * COLSPLIT;   // 1024
// q rows pre-scaled by 20*log2(e): accumulators are base-2 logits directly
constexpr float QSCALE = 20.0f * 1.4426950408889634f;
constexpr float D2SC = 28.853900817779268f;   // 20*log2(e)
constexpr float LN2 = 0.6931471805599453f;

constexpr int A_BYTES = BM * Dd * 2;                    // 196608
constexpr int B_OFF   = A_BYTES;
constexpr int SMEM_BYTES = A_BYTES + 2 * BN * BK * 2;   // 229376

// ===================== device scratch =====================
__device__ __align__(16) __nv_bfloat16 g_qn[(size_t)Nn * Dd];
__device__ __align__(16) __nv_bfloat16 g_cn[(size_t)Nn * Dd];
__device__ float g_rows[COLSPLIT][Nn];
__device__ float g_diag[Nn];   // exact fp32 diagonal, base-2 scaled

// ===================== helpers =====================
__device__ __forceinline__ uint32_t smem_u32(const void* p) {
    uint32_t a;
    asm("{ .reg .u64 t; cvta.to.shared.u64 t, %1; cvt.u32.u64 %0, t; }"
        : "=r"(a) : "l"(p));
    return a;
}

#define SMEM_SWIZZLE_128B(o) ((o) ^ (((o) >> 3) & 0x70))

__device__ __forceinline__ void cp16(uint32_t dst, const void* src) {
    asm volatile("cp.async.cg.shared.global [%0], [%1], 16;" :: "r"(dst), "l"(src));
}
#define CP_COMMIT asm volatile("cp.async.commit_group;" ::: "memory")
#define CP_WAIT0  asm volatile("cp.async.wait_group 0;" ::: "memory")

__device__ __forceinline__ void ldm4(uint32_t* r, uint32_t addr) {
    asm volatile("ldmatrix.sync.aligned.m8n8.x4.shared.b16 {%0,%1,%2,%3}, [%4];"
        : "=r"(r[0]), "=r"(r[1]), "=r"(r[2]), "=r"(r[3]) : "r"(addr));
}

__device__ __forceinline__ void mma16816(float* d, const uint32_t* a,
                                         uint32_t b0, uint32_t b1) {
    asm volatile(
        "mma.sync.aligned.m16n8k16.row.col.f32.bf16.bf16.f32 "
        "{%0,%1,%2,%3}, {%4,%5,%6,%7}, {%8,%9}, {%0,%1,%2,%3};"
        : "+f"(d[0]), "+f"(d[1]), "+f"(d[2]), "+f"(d[3])
        : "r"(a[0]), "r"(a[1]), "r"(a[2]), "r"(a[3]), "r"(b0), "r"(b1));
}

__device__ __forceinline__ float ex2f(float x) {
    float y;
    asm("ex2.approx.f32 %0, %1;" : "=f"(y) : "f"(x));
    return y;
}

// ===== kernel 1: normalize fp32 -> bf16 (q pre-scaled), exact diagonal =====
// One warp per row: float4 loads, shfl-only reduction, packed bf16x2 stores.
__global__ void __launch_bounds__(256) norm_kernel(const float* __restrict__ q,
                                                   const float* __restrict__ c) {
    const int lane = threadIdx.x & 31;
    const int row = blockIdx.x * 8 + (threadIdx.x >> 5);  // 0..8191

    const float4* qs = reinterpret_cast<const float4*>(q + (size_t)row * Dd);
    const float4* cs = reinterpret_cast<const float4*>(c + (size_t)row * Dd);

    float4 qv[6], cv[6];
    float qq = 0.f, cc = 0.f, qc = 0.f;
#pragma unroll
    for (int j = 0; j < 6; j++) {
        qv[j] = qs[lane + j * 32];
        cv[j] = cs[lane + j * 32];
        qq += qv[j].x * qv[j].x + qv[j].y * qv[j].y +
              qv[j].z * qv[j].z + qv[j].w * qv[j].w;
        cc += cv[j].x * cv[j].x + cv[j].y * cv[j].y +
              cv[j].z * cv[j].z + cv[j].w * cv[j].w;
        qc += qv[j].x * cv[j].x + qv[j].y * cv[j].y +
              qv[j].z * cv[j].z + qv[j].w * cv[j].w;
    }
#pragma unroll
    for (int o = 16; o; o >>= 1) {
        qq += __shfl_xor_sync(0xFFFFFFFFu, qq, o);
        cc += __shfl_xor_sync(0xFFFFFFFFu, cc, o);
        qc += __shfl_xor_sync(0xFFFFFFFFu, qc, o);
    }
    const float nq = fmaxf(sqrtf(qq), 1e-8f);
    const float nc = fmaxf(sqrtf(cc), 1e-8f);
    if (lane == 0) g_diag[row] = D2SC * qc / (nq * nc);

    const float sq = QSCALE / nq, sc = 1.0f / nc;
    uint2* qd = reinterpret_cast<uint2*>(g_qn + (size_t)row * Dd);
    uint2* cd = reinterpret_cast<uint2*>(g_cn + (size_t)row * Dd);
#pragma unroll
    for (int j = 0; j < 6; j++) {
        __nv_bfloat162 q0 = __float22bfloat162_rn(
            make_float2(qv[j].x * sq, qv[j].y * sq));
        __nv_bfloat162 q1 = __float22bfloat162_rn(
            make_float2(qv[j].z * sq, qv[j].w * sq));
        __nv_bfloat162 c0 = __float22bfloat162_rn(
            make_float2(cv[j].x * sc, cv[j].y * sc));
        __nv_bfloat162 c1 = __float22bfloat162_rn(
            make_float2(cv[j].z * sc, cv[j].w * sc));
        qd[lane + j * 32] = make_uint2(*(uint32_t*)&q0, *(uint32_t*)&q1);
        cd[lane + j * 32] = make_uint2(*(uint32_t*)&c0, *(uint32_t*)&c1);
    }
}

// ===================== kernel 2: persistent fused GEMM + exp2-rowsum =====================
// grid = #SMs. Contiguous job spans (bx-major) -> A-tile reuse.
// 8 warps: 4(M) x 2(N), 32x64 warp tiles. Tile epilogues are DEFERRED:
// acc is stashed into eacc at tile end and the exp2/rowsum work is spread
// over chunks kc=0..3 of the next tile (overlaps MUFU with tensor pipe).
__global__ void __launch_bounds__(256, 1) simcse_main() {
    extern __shared__ __align__(1024) uint8_t smem[];
    uint8_t* sA = smem;           // 12 chunks of [128 rows][128B] SW128 K-major
    uint8_t* sB = smem + B_OFF;   // 2 buffers of [128 rows][128B] SW128 K-major

    const int tid = threadIdx.x;
    const int lane = tid & 31;
    const int wid = tid >> 5;
    const int warp_m = wid >> 1;   // 0..3 (32 rows each)
    const int warp_n = wid & 1;    // 0..1 (64 cols each)

    const uint32_t sA_u = smem_u32(sA);
    const uint32_t sB_u = smem_u32(sB);

    // per-lane ldmatrix base offsets (bytes, pre-swizzle) — R2/R5-validated
    const uint32_t aoff0 = (uint32_t)((lane & 15) * 128 + (lane >> 4) * 16) +
                           (uint32_t)warp_m * 4096u;
    const uint32_t boff0 = (uint32_t)(((((lane >> 4) & 1) * 8) + (lane & 7)) * 128 +
                                      ((lane >> 3) & 1) * 16) +
                           (uint32_t)warp_n * 8192u;

    const int ncta = gridDim.x;
    const int lo = (int)(((long long)blockIdx.x * NJOBS) / ncta);
    const int hi = (int)(((long long)(blockIdx.x + 1) * NJOBS) / ncta);
    int prev_bx = -1;

    float acc[2][8][4];
    float eacc[2][8][4];
#pragma unroll
    for (int mt = 0; mt < 2; mt++)
#pragma unroll
        for (int nt = 0; nt < 8; nt++)
#pragma unroll
            for (int d = 0; d < 4; d++) acc[mt][nt][d] = 0.f;

#pragma unroll 1
    for (int job = lo; job < hi; job++) {
        const int bx = job >> 4;       // row block 0..63
        const int by = job & 15;       // col split 0..15

        // ---- stage A on bx change: 128 Q rows (192KB) via cp.async ----
        if (bx != prev_bx) {
            const __nv_bfloat16* qbase = g_qn + (size_t)bx * BM * Dd;
#pragma unroll 4
            for (int i = 0; i < 48; i++) {
                int idx = tid + i * 256;        // 0..12287 (16B units)
                int kc = idx >> 10;
                int pos = idx & 1023;
                int r = pos >> 3, c = pos & 7;
                const void* src = qbase + (size_t)r * Dd + kc * BK + c * 8;
                uint32_t dst = sA_u + kc * 16384 +
                               SMEM_SWIZZLE_128B((uint32_t)(r * 128 + c * 16));
                cp16(dst, src);
            }
            prev_bx = bx;
        }

        const __nv_bfloat16* cquad = g_cn + (size_t)by * CHUNKS * BN * Dd;

        auto loadB = [&](int g, int buf) {
            const int t = g / NKC, kc = g % NKC;
            const __nv_bfloat16* cb = cquad + (size_t)t * BN * Dd + kc * BK;
#pragma unroll
            for (int i = 0; i < 4; i++) {
                int pos = tid + i * 256;        // 0..1023
                int r = pos >> 3, c = pos & 7;
                cp16(sB_u + buf * 16384 +
                         SMEM_SWIZZLE_128B((uint32_t)(r * 128 + c * 16)),
                     cb + (size_t)r * Dd + c * 8);
            }
            CP_COMMIT;
        };

        loadB(0, 0);  // (A's cp.asyncs, if any, join this commit group)

        float rsum[2][2] = {{0.f, 0.f}, {0.f, 0.f}};
        bool pending = false;

        // one 64-K chunk: wait, publish, prefetch next B, ldm+mma
        auto chunk = [&](int g, int kc) {
            const int buf = g & 1;
            CP_WAIT0;            // this chunk's B tile (and A if staged) resident
            __syncthreads();     // publish buf to all threads; protect buf^1
            if (g + 1 < TOT) loadB(g + 1, buf ^ 1);

            const uint32_t abase = sA_u + (uint32_t)kc * 16384u;
            const uint32_t bbase = sB_u + (uint32_t)buf * 16384u;

            uint32_t a[2][2][4], b[2][4][4];
#pragma unroll
            for (int mt = 0; mt < 2; mt++)
                ldm4(a[0][mt], abase + SMEM_SWIZZLE_128B(aoff0 + (uint32_t)(mt * 2048)));
#pragma unroll
            for (int ntp = 0; ntp < 4; ntp++)
                ldm4(b[0][ntp], bbase + SMEM_SWIZZLE_128B(boff0 + (uint32_t)(ntp * 2048)));

#pragma unroll
            for (int kk = 0; kk < 4; kk++) {
                const int cur = kk & 1, nxt = cur ^ 1;
                if (kk < 3) {
#pragma unroll
                    for (int mt = 0; mt < 2; mt++)
                        ldm4(a[nxt][mt], abase + SMEM_SWIZZLE_128B(
                                 aoff0 + (uint32_t)(mt * 2048 + (kk + 1) * 32)));
#pragma unroll
                    for (int ntp = 0; ntp < 4; ntp++)
                        ldm4(b[nxt][ntp], bbase + SMEM_SWIZZLE_128B(
                                 boff0 + (uint32_t)(ntp * 2048 + (kk + 1) * 32)));
                }
#pragma unroll
                for (int mt = 0; mt < 2; mt++)
#pragma unroll
                    for (int ntp = 0; ntp < 4; ntp++) {
                        mma16816(acc[mt][2 * ntp + 0], a[cur][mt],
                                 b[cur][ntp][0], b[cur][ntp][1]);
                        mma16816(acc[mt][2 * ntp + 1], a[cur][mt],
                                 b[cur][ntp][2], b[cur][ntp][3]);
                    }
            }
        };

#pragma unroll 1
        for (int t = 0; t < CHUNKS; t++) {
            // peeled kc=0..3: carry the previous tile's epilogue slices
#pragma unroll
            for (int kcp = 0; kcp < 4; kcp++) {
                chunk(t * NKC + kcp, kcp);
                if (pending) {
#pragma unroll
                    for (int mt = 0; mt < 2; mt++)
#pragma unroll
                        for (int j = 0; j < 2; j++) {
                            const int nt = 2 * kcp + j;  // static
#pragma unroll
                            for (int d = 0; d < 4; d++)
                                rsum[mt][d >> 1] += ex2f(eacc[mt][nt][d]);
                        }
                }
            }
#pragma unroll 1
            for (int kc = 4; kc < NKC; kc++) chunk(t * NKC + kc, kc);

            // tile end: stash accumulators, clear for next tile
#pragma unroll
            for (int mt = 0; mt < 2; mt++)
#pragma unroll
                for (int nt = 0; nt < 8; nt++)
#pragma unroll
                    for (int d = 0; d < 4; d++) {
                        eacc[mt][nt][d] = acc[mt][nt][d];
                        acc[mt][nt][d] = 0.f;
                    }
            pending = true;
        }

        // final (non-overlapped) epilogue for the job's last tile
#pragma unroll
        for (int mt = 0; mt < 2; mt++)
#pragma unroll
            for (int nt = 0; nt < 8; nt++)
#pragma unroll
                for (int d = 0; d < 4; d++)
                    rsum[mt][d >> 1] += ex2f(eacc[mt][nt][d]);

        // ---- per-job reduce: quad shuffle, then across the 2 N-warps ----
#pragma unroll
        for (int mt = 0; mt < 2; mt++)
#pragma unroll
            for (int h = 0; h < 2; h++) {
                float v = rsum[mt][h];
                v += __shfl_xor_sync(0xFFFFFFFFu, v, 1);
                v += __shfl_xor_sync(0xFFFFFFFFu, v, 2);
                rsum[mt][h] = v;
            }

        float* sred = (float*)sB;    // B buffers are free after last chunk
        __syncthreads();             // all warps done with compute/B reads
        if ((lane & 3) == 0) {
#pragma unroll
            for (int mt = 0; mt < 2; mt++)
#pragma unroll
                for (int h = 0; h < 2; h++) {
                    int rl = warp_m * 32 + mt * 16 + h * 8 + (lane >> 2);
                    sred[rl * 2 + warp_n] = rsum[mt][h];
                }
        }
        __syncthreads();
        if (tid < BM) g_rows[by][bx * BM + tid] = sred[tid * 2] + sred[tid * 2 + 1];
        __syncthreads();  // sred reads done before next job's loadB overwrites sB
    }
}

// ===================== kernel 3: loss reduction =====================
__global__ void __launch_bounds__(256) loss_kernel(float* __restrict__ out) {
    int tid = threadIdx.x;
    float acc = 0.f;
    for (int i = tid; i < Nn; i += 256) {
        float r = 0.f;
#pragma unroll
        for (int s = 0; s < COLSPLIT; s++) r += g_rows[s][i];
        acc += logf(r) - g_diag[i] * LN2;   // diag is base-2 scaled (exact fp32)
    }
#pragma unroll
    for (int o = 16; o; o >>= 1) acc += __shfl_xor_sync(0xFFFFFFFFu, acc, o);
    __shared__ float sred[8];
    if ((tid & 31) == 0) sred[tid >> 5] = acc;
    __syncthreads();
    if (tid == 0) {
        float tot = 0.f;
#pragma unroll
        for (int i = 0; i < 8; i++) tot += sred[i];
        out[0] = tot * (1.0f / (float)Nn);
    }
}

// ===================== launch =====================
extern "C" void kernel_launch(void* const* d_in, const int* in_sizes, int n_in,
                              void* d_out, int out_size) {
    const float* q = (const float*)d_in[0];
    const float* c = (const float*)d_in[1];
    float* out = (float*)d_out;

    cudaFuncSetAttribute(simcse_main, cudaFuncAttributeMaxDynamicSharedMemorySize,
                         SMEM_BYTES);

    int nsm = 148;
    cudaDeviceGetAttribute(&nsm, cudaDevAttrMultiProcessorCount, 0);
    if (nsm < 1) nsm = 148;

    norm_kernel<<<Nn / 8, 256>>>(q, c);
    simcse_main<<<nsm, 256, SMEM_BYTES>>>();
    loss_kernel<<<1, 256>>>(out);
}

// round 14
// speedup vs baseline: 2.8731x; 1.0250x over previous
#include <cuda_runtime.h>
#include <cuda_bf16.h>
#include <cstdint>

// ===================== problem constants =====================
constexpr int Nn = 8192;
constexpr int Dd = 768;
constexpr int BM = 128;            // Q rows per job
constexpr int BN = 128;            // C cols per tile
constexpr int BK = 64;             // K per SMEM chunk (64 bf16 = 128B rows)
constexpr int NKC = Dd / BK;       // 12 K-chunks
constexpr int COLSPLIT = 16;       // by range
constexpr int CHUNKS = (Nn / BN) / COLSPLIT;  // 4 col tiles per job
constexpr int TOT = CHUNKS * NKC;  // 48 B-chunk iterations per job
constexpr int NJOBS = (Nn / BM) * COLSPLIT;   // 1024
// q rows pre-scaled by 20*log2(e): accumulators are base-2 logits directly
constexpr float QSCALE = 20.0f * 1.4426950408889634f;
constexpr float D2SC = 28.853900817779268f;   // 20*log2(e)
constexpr float LN2 = 0.6931471805599453f;

constexpr int A_BYTES = BM * Dd * 2;                    // 196608
constexpr int B_OFF   = A_BYTES;
constexpr int SMEM_BYTES = A_BYTES + 2 * BN * BK * 2;   // 229376

// ===================== device scratch =====================
__device__ __align__(16) __nv_bfloat16 g_qn[(size_t)Nn * Dd];
__device__ __align__(16) __nv_bfloat16 g_cn[(size_t)Nn * Dd];
__device__ float g_rows[COLSPLIT][Nn];
__device__ float g_diag[Nn];   // exact fp32 diagonal, base-2 scaled

// ===================== helpers =====================
__device__ __forceinline__ uint32_t smem_u32(const void* p) {
    uint32_t a;
    asm("{ .reg .u64 t; cvta.to.shared.u64 t, %1; cvt.u32.u64 %0, t; }"
        : "=r"(a) : "l"(p));
    return a;
}

#define SMEM_SWIZZLE_128B(o) ((o) ^ (((o) >> 3) & 0x70))

__device__ __forceinline__ void cp16(uint32_t dst, const void* src) {
    asm volatile("cp.async.cg.shared.global [%0], [%1], 16;" :: "r"(dst), "l"(src));
}
#define CP_COMMIT asm volatile("cp.async.commit_group;" ::: "memory")
#define CP_WAIT0  asm volatile("cp.async.wait_group 0;" ::: "memory")

__device__ __forceinline__ void ldm4(uint32_t* r, uint32_t addr) {
    asm volatile("ldmatrix.sync.aligned.m8n8.x4.shared.b16 {%0,%1,%2,%3}, [%4];"
        : "=r"(r[0]), "=r"(r[1]), "=r"(r[2]), "=r"(r[3]) : "r"(addr));
}

__device__ __forceinline__ void mma16816(float* d, const uint32_t* a,
                                         uint32_t b0, uint32_t b1) {
    asm volatile(
        "mma.sync.aligned.m16n8k16.row.col.f32.bf16.bf16.f32 "
        "{%0,%1,%2,%3}, {%4,%5,%6,%7}, {%8,%9}, {%0,%1,%2,%3};"
        : "+f"(d[0]), "+f"(d[1]), "+f"(d[2]), "+f"(d[3])
        : "r"(a[0]), "r"(a[1]), "r"(a[2]), "r"(a[3]), "r"(b0), "r"(b1));
}

__device__ __forceinline__ float ex2f(float x) {
    float y;
    asm("ex2.approx.f32 %0, %1;" : "=f"(y) : "f"(x));
    return y;
}

// ===== kernel 1: normalize fp32 -> bf16 (q pre-scaled), exact diagonal =====
// One warp per row: float4 loads, shfl-only reduction, packed bf16x2 stores.
__global__ void __launch_bounds__(256) norm_kernel(const float* __restrict__ q,
                                                   const float* __restrict__ c) {
    const int lane = threadIdx.x & 31;
    const int row = blockIdx.x * 8 + (threadIdx.x >> 5);  // 0..8191

    const float4* qs = reinterpret_cast<const float4*>(q + (size_t)row * Dd);
    const float4* cs = reinterpret_cast<const float4*>(c + (size_t)row * Dd);

    float4 qv[6], cv[6];
    float qq = 0.f, cc = 0.f, qc = 0.f;
#pragma unroll
    for (int j = 0; j < 6; j++) {
        qv[j] = qs[lane + j * 32];
        cv[j] = cs[lane + j * 32];
        qq += qv[j].x * qv[j].x + qv[j].y * qv[j].y +
              qv[j].z * qv[j].z + qv[j].w * qv[j].w;
        cc += cv[j].x * cv[j].x + cv[j].y * cv[j].y +
              cv[j].z * cv[j].z + cv[j].w * cv[j].w;
        qc += qv[j].x * cv[j].x + qv[j].y * cv[j].y +
              qv[j].z * cv[j].z + qv[j].w * cv[j].w;
    }
#pragma unroll
    for (int o = 16; o; o >>= 1) {
        qq += __shfl_xor_sync(0xFFFFFFFFu, qq, o);
        cc += __shfl_xor_sync(0xFFFFFFFFu, cc, o);
        qc += __shfl_xor_sync(0xFFFFFFFFu, qc, o);
    }
    const float nq = fmaxf(sqrtf(qq), 1e-8f);
    const float nc = fmaxf(sqrtf(cc), 1e-8f);
    if (lane == 0) g_diag[row] = D2SC * qc / (nq * nc);

    const float sq = QSCALE / nq, sc = 1.0f / nc;
    uint2* qd = reinterpret_cast<uint2*>(g_qn + (size_t)row * Dd);
    uint2* cd = reinterpret_cast<uint2*>(g_cn + (size_t)row * Dd);
#pragma unroll
    for (int j = 0; j < 6; j++) {
        __nv_bfloat162 q0 = __float22bfloat162_rn(
            make_float2(qv[j].x * sq, qv[j].y * sq));
        __nv_bfloat162 q1 = __float22bfloat162_rn(
            make_float2(qv[j].z * sq, qv[j].w * sq));
        __nv_bfloat162 c0 = __float22bfloat162_rn(
            make_float2(cv[j].x * sc, cv[j].y * sc));
        __nv_bfloat162 c1 = __float22bfloat162_rn(
            make_float2(cv[j].z * sc, cv[j].w * sc));
        qd[lane + j * 32] = make_uint2(*(uint32_t*)&q0, *(uint32_t*)&q1);
        cd[lane + j * 32] = make_uint2(*(uint32_t*)&c0, *(uint32_t*)&c1);
    }
}

// ===================== kernel 2: persistent fused GEMM + exp2-rowsum =====================
// grid = #SMs. Contiguous job spans (bx-major) -> A-tile reuse.
// 8 warps: 4(M) x 2(N), 32x64 warp tiles. Tile epilogues are DEFERRED:
// acc is stashed into eacc at tile end and the exp2/rowsum work is spread
// over chunks kc=0..3 of the next tile (overlaps MUFU with tensor pipe).
__global__ void __launch_bounds__(256, 1) simcse_main() {
    extern __shared__ __align__(1024) uint8_t smem[];
    uint8_t* sA = smem;           // 12 chunks of [128 rows][128B] SW128 K-major
    uint8_t* sB = smem + B_OFF;   // 2 buffers of [128 rows][128B] SW128 K-major

    const int tid = threadIdx.x;
    const int lane = tid & 31;
    const int wid = tid >> 5;
    const int warp_m = wid >> 1;   // 0..3 (32 rows each)
    const int warp_n = wid & 1;    // 0..1 (64 cols each)

    const uint32_t sA_u = smem_u32(sA);
    const uint32_t sB_u = smem_u32(sB);

    // per-lane ldmatrix base offsets (bytes, pre-swizzle) — R2/R5-validated
    const uint32_t aoff0 = (uint32_t)((lane & 15) * 128 + (lane >> 4) * 16) +
                           (uint32_t)warp_m * 4096u;
    const uint32_t boff0 = (uint32_t)(((((lane >> 4) & 1) * 8) + (lane & 7)) * 128 +
                                      ((lane >> 3) & 1) * 16) +
                           (uint32_t)warp_n * 8192u;

    const int ncta = gridDim.x;
    const int lo = (int)(((long long)blockIdx.x * NJOBS) / ncta);
    const int hi = (int)(((long long)(blockIdx.x + 1) * NJOBS) / ncta);
    int prev_bx = -1;

    float acc[2][8][4];
    float eacc[2][8][4];
#pragma unroll
    for (int mt = 0; mt < 2; mt++)
#pragma unroll
        for (int nt = 0; nt < 8; nt++)
#pragma unroll
            for (int d = 0; d < 4; d++) acc[mt][nt][d] = 0.f;

#pragma unroll 1
    for (int job = lo; job < hi; job++) {
        const int bx = job >> 4;       // row block 0..63
        const int by = job & 15;       // col split 0..15

        // ---- stage A on bx change: 128 Q rows (192KB) via cp.async ----
        if (bx != prev_bx) {
            const __nv_bfloat16* qbase = g_qn + (size_t)bx * BM * Dd;
#pragma unroll 4
            for (int i = 0; i < 48; i++) {
                int idx = tid + i * 256;        // 0..12287 (16B units)
                int kc = idx >> 10;
                int pos = idx & 1023;
                int r = pos >> 3, c = pos & 7;
                const void* src = qbase + (size_t)r * Dd + kc * BK + c * 8;
                uint32_t dst = sA_u + kc * 16384 +
                               SMEM_SWIZZLE_128B((uint32_t)(r * 128 + c * 16));
                cp16(dst, src);
            }
            prev_bx = bx;
        }

        const __nv_bfloat16* cquad = g_cn + (size_t)by * CHUNKS * BN * Dd;

        auto loadB = [&](int g, int buf) {
            const int t = g / NKC, kc = g % NKC;
            const __nv_bfloat16* cb = cquad + (size_t)t * BN * Dd + kc * BK;
#pragma unroll
            for (int i = 0; i < 4; i++) {
                int pos = tid + i * 256;        // 0..1023
                int r = pos >> 3, c = pos & 7;
                cp16(sB_u + buf * 16384 +
                         SMEM_SWIZZLE_128B((uint32_t)(r * 128 + c * 16)),
                     cb + (size_t)r * Dd + c * 8);
            }
            CP_COMMIT;
        };

        loadB(0, 0);  // (A's cp.asyncs, if any, join this commit group)

        float rsum[2][2] = {{0.f, 0.f}, {0.f, 0.f}};
        bool pending = false;

        // one 64-K chunk: wait, publish, prefetch next B, ldm+mma
        auto chunk = [&](int g, int kc) {
            const int buf = g & 1;
            CP_WAIT0;            // this chunk's B tile (and A if staged) resident
            __syncthreads();     // publish buf to all threads; protect buf^1
            if (g + 1 < TOT) loadB(g + 1, buf ^ 1);

            const uint32_t abase = sA_u + (uint32_t)kc * 16384u;
            const uint32_t bbase = sB_u + (uint32_t)buf * 16384u;

            uint32_t a[2][2][4], b[2][4][4];
#pragma unroll
            for (int mt = 0; mt < 2; mt++)
                ldm4(a[0][mt], abase + SMEM_SWIZZLE_128B(aoff0 + (uint32_t)(mt * 2048)));
#pragma unroll
            for (int ntp = 0; ntp < 4; ntp++)
                ldm4(b[0][ntp], bbase + SMEM_SWIZZLE_128B(boff0 + (uint32_t)(ntp * 2048)));

#pragma unroll
            for (int kk = 0; kk < 4; kk++) {
                const int cur = kk & 1, nxt = cur ^ 1;
                if (kk < 3) {
#pragma unroll
                    for (int mt = 0; mt < 2; mt++)
                        ldm4(a[nxt][mt], abase + SMEM_SWIZZLE_128B(
                                 aoff0 + (uint32_t)(mt * 2048 + (kk + 1) * 32)));
#pragma unroll
                    for (int ntp = 0; ntp < 4; ntp++)
                        ldm4(b[nxt][ntp], bbase + SMEM_SWIZZLE_128B(
                                 boff0 + (uint32_t)(ntp * 2048 + (kk + 1) * 32)));
                }
#pragma unroll
                for (int mt = 0; mt < 2; mt++)
#pragma unroll
                    for (int ntp = 0; ntp < 4; ntp++) {
                        mma16816(acc[mt][2 * ntp + 0], a[cur][mt],
                                 b[cur][ntp][0], b[cur][ntp][1]);
                        mma16816(acc[mt][2 * ntp + 1], a[cur][mt],
                                 b[cur][ntp][2], b[cur][ntp][3]);
                    }
            }
        };

#pragma unroll 1
        for (int t = 0; t < CHUNKS; t++) {
            // peeled kc=0..3: carry the previous tile's epilogue slices
#pragma unroll
            for (int kcp = 0; kcp < 4; kcp++) {
                chunk(t * NKC + kcp, kcp);
                if (pending) {
#pragma unroll
                    for (int mt = 0; mt < 2; mt++)
#pragma unroll
                        for (int j = 0; j < 2; j++) {
                            const int nt = 2 * kcp + j;  // static
#pragma unroll
                            for (int d = 0; d < 4; d++)
                                rsum[mt][d >> 1] += ex2f(eacc[mt][nt][d]);
                        }
                }
            }
#pragma unroll 1
            for (int kc = 4; kc < NKC; kc++) chunk(t * NKC + kc, kc);

            // tile end: stash accumulators, clear for next tile
#pragma unroll
            for (int mt = 0; mt < 2; mt++)
#pragma unroll
                for (int nt = 0; nt < 8; nt++)
#pragma unroll
                    for (int d = 0; d < 4; d++) {
                        eacc[mt][nt][d] = acc[mt][nt][d];
                        acc[mt][nt][d] = 0.f;
                    }
            pending = true;
        }

        // final (non-overlapped) epilogue for the job's last tile
#pragma unroll
        for (int mt = 0; mt < 2; mt++)
#pragma unroll
            for (int nt = 0; nt < 8; nt++)
#pragma unroll
                for (int d = 0; d < 4; d++)
                    rsum[mt][d >> 1] += ex2f(eacc[mt][nt][d]);

        // ---- per-job reduce: quad shuffle, then across the 2 N-warps ----
#pragma unroll
        for (int mt = 0; mt < 2; mt++)
#pragma unroll
            for (int h = 0; h < 2; h++) {
                float v = rsum[mt][h];
                v += __shfl_xor_sync(0xFFFFFFFFu, v, 1);
                v += __shfl_xor_sync(0xFFFFFFFFu, v, 2);
                rsum[mt][h] = v;
            }

        float* sred = (float*)sB;    // B buffers are free after last chunk
        __syncthreads();             // all warps done with compute/B reads
        if ((lane & 3) == 0) {
#pragma unroll
            for (int mt = 0; mt < 2; mt++)
#pragma unroll
                for (int h = 0; h < 2; h++) {
                    int rl = warp_m * 32 + mt * 16 + h * 8 + (lane >> 2);
                    sred[rl * 2 + warp_n] = rsum[mt][h];
                }
        }
        __syncthreads();
        if (tid < BM) g_rows[by][bx * BM + tid] = sred[tid * 2] + sred[tid * 2 + 1];
        __syncthreads();  // sred reads done before next job's loadB overwrites sB
    }
}

// ===================== kernel 3: loss reduction (1024 threads) =====================
__global__ void __launch_bounds__(1024) loss_kernel(float* __restrict__ out) {
    int tid = threadIdx.x;
    float acc = 0.f;
#pragma unroll 1
    for (int i = tid; i < Nn; i += 1024) {
        float r = 0.f;
#pragma unroll
        for (int s = 0; s < COLSPLIT; s++) r += g_rows[s][i];
        acc += logf(r) - g_diag[i] * LN2;   // diag is base-2 scaled (exact fp32)
    }
#pragma unroll
    for (int o = 16; o; o >>= 1) acc += __shfl_xor_sync(0xFFFFFFFFu, acc, o);
    __shared__ float sred[32];
    if ((tid & 31) == 0) sred[tid >> 5] = acc;
    __syncthreads();
    if (tid < 32) {
        float v = sred[tid];
#pragma unroll
        for (int o = 16; o; o >>= 1) v += __shfl_xor_sync(0xFFFFFFFFu, v, o);
        if (tid == 0) out[0] = v * (1.0f / (float)Nn);
    }
}

// ===================== launch =====================
extern "C" void kernel_launch(void* const* d_in, const int* in_sizes, int n_in,
                              void* d_out, int out_size) {
    const float* q = (const float*)d_in[0];
    const float* c = (const float*)d_in[1];
    float* out = (float*)d_out;

    cudaFuncSetAttribute(simcse_main, cudaFuncAttributeMaxDynamicSharedMemorySize,
                         SMEM_BYTES);

    int nsm = 148;
    cudaDeviceGetAttribute(&nsm, cudaDevAttrMultiProcessorCount, 0);
    if (nsm < 1) nsm = 148;

    norm_kernel<<<Nn / 8, 256>>>(q, c);
    simcse_main<<<nsm, 256, SMEM_BYTES>>>();
    loss_kernel<<<1, 1024>>>(out);
}